// round 8
// baseline (speedup 1.0000x reference)
#include <cuda_runtime.h>
#include <stdint.h>

#define BATCH 4
#define SEQ   2048
#define NH    16
#define DHEAD 64
#define DMODEL 1024

// Scratch (allocation-free rule: __device__ globals)
__device__ float g_q[(size_t)BATCH*NH*SEQ*DHEAD];
__device__ float g_k[(size_t)BATCH*NH*SEQ*DHEAD];
__device__ float g_v[(size_t)BATCH*NH*SEQ*DHEAD];
__device__ float g_att[(size_t)BATCH*SEQ*DMODEL];
__device__ float g_x [(size_t)BATCH*SEQ*DMODEL];            // tf32-rounded x
__device__ float g_wq[(size_t)NH*DMODEL*DHEAD];             // [h][d][m] rounded
__device__ float g_wk[(size_t)NH*DMODEL*DHEAD];
__device__ float g_wv[(size_t)NH*DMODEL*DHEAD];
__device__ float g_wo[(size_t)DMODEL*DMODEL];               // [n][k] rounded

__device__ __forceinline__ unsigned f2tf(float f){
    unsigned u;
    asm("cvt.rna.tf32.f32 %0, %1;" : "=r"(u) : "f"(f));
    return u;
}
__device__ __forceinline__ float rtf(float f){ return __uint_as_float(f2tf(f)); }

__device__ __forceinline__ uint32_t s2u(const void* p){
    return (uint32_t)__cvta_generic_to_shared(p);
}
__device__ __forceinline__ void ldsm4(unsigned r[4], uint32_t addr){
    asm volatile("ldmatrix.sync.aligned.m8n8.x4.shared.b16 {%0,%1,%2,%3}, [%4];"
        : "=r"(r[0]), "=r"(r[1]), "=r"(r[2]), "=r"(r[3]) : "r"(addr));
}
__device__ __forceinline__ void mma_tf32(float* d, const unsigned* a, const unsigned* b){
    asm volatile(
        "mma.sync.aligned.m16n8k8.row.col.f32.tf32.tf32.f32 "
        "{%0,%1,%2,%3},{%4,%5,%6,%7},{%8,%9},{%0,%1,%2,%3};\n"
        : "+f"(d[0]), "+f"(d[1]), "+f"(d[2]), "+f"(d[3])
        : "r"(a[0]), "r"(a[1]), "r"(a[2]), "r"(a[3]), "r"(b[0]), "r"(b[1]));
}
__device__ __forceinline__ void cpa16(uint32_t dst, const void* src){
    asm volatile("cp.async.cg.shared.global [%0], [%1], 16;\n" :: "r"(dst), "l"(src));
}
__device__ __forceinline__ void cpa_commit(){
    asm volatile("cp.async.commit_group;\n" ::: "memory");
}
template<int N>
__device__ __forceinline__ void cpa_wait(){
    asm volatile("cp.async.wait_group %0;\n" :: "n"(N) : "memory");
}

// ---------------------------------------------------------------------------
// Pre-round x into g_x (tf32 rounding applied once, outside the GEMM loops)
// ---------------------------------------------------------------------------
__global__ void preround_x_kernel(const float* __restrict__ x)
{
    const size_t n4 = (size_t)BATCH*SEQ*DMODEL/4;
    for (size_t i = blockIdx.x*blockDim.x + threadIdx.x; i < n4;
         i += (size_t)gridDim.x*blockDim.x) {
        float4 v = ((const float4*)x)[i];
        v.x = rtf(v.x); v.y = rtf(v.y); v.z = rtf(v.z); v.w = rtf(v.w);
        ((float4*)g_x)[i] = v;
    }
}

// ---------------------------------------------------------------------------
// Transpose + round: in[batch][rows][cols] -> out[batch][cols][rows]
// ---------------------------------------------------------------------------
__global__ void trw_kernel(const float* __restrict__ in, float* __restrict__ out,
                           int rows, int cols)
{
    __shared__ float tile[32][33];
    const size_t boff = (size_t)blockIdx.z * rows * cols;
    const int c0 = blockIdx.x*32, r0 = blockIdx.y*32;
    const int tx = threadIdx.x, ty = threadIdx.y;   // 32 x 8
    #pragma unroll
    for (int i = 0; i < 32; i += 8)
        tile[ty+i][tx] = in[boff + (size_t)(r0+ty+i)*cols + c0+tx];
    __syncthreads();
    #pragma unroll
    for (int i = 0; i < 32; i += 8)
        out[boff + (size_t)(c0+ty+i)*rows + r0+tx] = rtf(tile[tx][ty+i]);
}

// ---------------------------------------------------------------------------
// tf32 GEMM core: C[128x64] = A[128xK] * B[K x 64] + bias
// A: [m][k] pre-rounded. B: [n][k] pre-rounded (ldb = k-stride).
// 3-stage cp.async pipeline, SW128 XOR swizzle, LDSM fragments.
// mode: 0 = plain f32 out; 1 = tf32-rounded out; 2 = x0.125 then rounded.
// ---------------------------------------------------------------------------
#define AST 1024     // uint4 per A stage
#define BST 512      // uint4 per B stage
#define GEMM_SMEM ((3*AST + 3*BST)*16)   // 73728 B

__device__ __forceinline__ void gemm128x64(
    const float* __restrict__ A, int lda,
    const float* __restrict__ B, int ldb,
    const float* __restrict__ bias,
    float* __restrict__ C, int ldc, int K, int mode)
{
    extern __shared__ uint4 sm4[];
    const uint32_t as_b = s2u(sm4);
    const uint32_t bs_b = as_b + 3*AST*16;

    const int t = threadIdx.x, lane = t & 31, warp = t >> 5;
    const int wm = warp >> 1, wn = warp & 1;
    const int g  = lane >> 2, tig = lane & 3;

    // async loaders
    const int ar = t >> 1, ac = (t & 1) * 4;   // A: row, chunk base (+j, j<4)
    const int br = t & 63, bc = (t >> 6) * 2;  // B: n row, chunk base (+j, j<2)
    const float* Asrc = A + (size_t)ar*lda + ac*4;
    const float* Bsrc = B + (size_t)br*ldb + bc*4;
    uint32_t a_dst[4], b_dst[2];
    #pragma unroll
    for (int j = 0; j < 4; j++)
        a_dst[j] = as_b + (uint32_t)(ar*8 + ((ac+j) ^ (ar&7)))*16u;
    #pragma unroll
    for (int j = 0; j < 2; j++)
        b_dst[j] = bs_b + (uint32_t)(br*8 + ((bc+j) ^ (br&7)))*16u;

    const int a_row0 = wm*32 +      (lane & 15);
    const int a_row1 = wm*32 + 16 + (lane & 15);
    const int b_row0 = wn*32 +      (lane & 15);
    const int b_row1 = wn*32 + 16 + (lane & 15);
    const int csel   = lane >> 4;

    float acc[2][4][4];
    #pragma unroll
    for (int i = 0; i < 2; i++)
        #pragma unroll
        for (int j = 0; j < 4; j++)
            #pragma unroll
            for (int c = 0; c < 4; c++) acc[i][j][c] = 0.f;

    const int iters = K / 32;

    // prologue: stages 0,1
    #pragma unroll
    for (int s = 0; s < 2; s++) {
        #pragma unroll
        for (int j = 0; j < 4; j++)
            cpa16(a_dst[j] + (uint32_t)s*(AST*16), Asrc + s*32 + j*4);
        #pragma unroll
        for (int j = 0; j < 2; j++)
            cpa16(b_dst[j] + (uint32_t)s*(BST*16), Bsrc + s*32 + j*4);
        cpa_commit();
    }

    for (int it = 0; it < iters; it++) {
        const int st = it % 3;
        cpa_wait<1>();
        __syncthreads();

        const uint32_t as_s = as_b + (uint32_t)st*(AST*16);
        const uint32_t bs_s = bs_b + (uint32_t)st*(BST*16);
        #pragma unroll
        for (int s = 0; s < 4; s++) {
            const int cl = s*2 + csel;
            unsigned af[2][4], bf[2][4];
            ldsm4(af[0], as_s + (uint32_t)(a_row0*8 + (cl ^ (a_row0&7)))*16u);
            ldsm4(af[1], as_s + (uint32_t)(a_row1*8 + (cl ^ (a_row1&7)))*16u);
            ldsm4(bf[0], bs_s + (uint32_t)(b_row0*8 + (cl ^ (b_row0&7)))*16u);
            ldsm4(bf[1], bs_s + (uint32_t)(b_row1*8 + (cl ^ (b_row1&7)))*16u);
            #pragma unroll
            for (int mt = 0; mt < 2; mt++)
                #pragma unroll
                for (int nt = 0; nt < 4; nt++) {
                    unsigned b2[2] = { bf[nt>>1][nt&1], bf[nt>>1][(nt&1)|2] };
                    mma_tf32(acc[mt][nt], af[mt], b2);
                }
        }

        if (it + 2 < iters) {
            const int sn = (it + 2) % 3;
            #pragma unroll
            for (int j = 0; j < 4; j++)
                cpa16(a_dst[j] + (uint32_t)sn*(AST*16), Asrc + (it+2)*32 + j*4);
            #pragma unroll
            for (int j = 0; j < 2; j++)
                cpa16(b_dst[j] + (uint32_t)sn*(BST*16), Bsrc + (it+2)*32 + j*4);
        }
        cpa_commit();
    }

    // epilogue
    #pragma unroll
    for (int mt = 0; mt < 2; mt++) {
        #pragma unroll
        for (int nt = 0; nt < 4; nt++) {
            const int row = wm*32 + mt*16 + g;
            const int col = wn*32 + nt*8 + 2*tig;
            const float b0 = bias[col], b1 = bias[col+1];
            float v0 = acc[mt][nt][0] + b0, v1 = acc[mt][nt][1] + b1;
            float v2 = acc[mt][nt][2] + b0, v3 = acc[mt][nt][3] + b1;
            if (mode != 0) {
                const float s = (mode == 2) ? 0.125f : 1.0f;
                v0 = rtf(v0*s); v1 = rtf(v1*s); v2 = rtf(v2*s); v3 = rtf(v3*s);
            }
            *(float2*)(C + (size_t)row*ldc + col)     = make_float2(v0, v1);
            *(float2*)(C + (size_t)(row+8)*ldc + col) = make_float2(v2, v3);
        }
    }
}

// ---------------------------------------------------------------------------
// QKV projection (outputs pre-rounded; Q also pre-scaled by 1/8)
// ---------------------------------------------------------------------------
__global__ __launch_bounds__(256, 2) void qkv_kernel(
    const float* __restrict__ Qb, const float* __restrict__ Kb,
    const float* __restrict__ Vb)
{
    const int proj = blockIdx.y >> 4;
    const int h    = blockIdx.y & 15;

    const float* W; const float* bias; float* out; int mode;
    if (proj == 0)      { W = g_wq; bias = Qb; out = g_q; mode = 2; }
    else if (proj == 1) { W = g_wk; bias = Kb; out = g_k; mode = 1; }
    else                { W = g_wv; bias = Vb; out = g_v; mode = 1; }

    const int rbase = blockIdx.x * 128;
    const int b     = rbase / SEQ;
    const int srow  = rbase % SEQ;

    gemm128x64(g_x + (size_t)rbase * DMODEL, DMODEL,
               W + (size_t)h * DMODEL * DHEAD, DMODEL,
               bias + h * DHEAD,
               out + (((size_t)(b*NH + h))*SEQ + srow) * DHEAD, DHEAD,
               DMODEL, mode);
}

// ---------------------------------------------------------------------------
// Output projection
// ---------------------------------------------------------------------------
__global__ __launch_bounds__(256, 2) void oproj_kernel(
    const float* __restrict__ Ob, float* __restrict__ out)
{
    const int rbase = blockIdx.x * 128;
    const int nbase = blockIdx.y * 64;
    gemm128x64(g_att + (size_t)rbase * DMODEL, DMODEL,
               g_wo + (size_t)nbase * DMODEL, DMODEL,
               Ob + nbase,
               out + (size_t)rbase * DMODEL + nbase, DMODEL,
               DMODEL, 0);
}

// ---------------------------------------------------------------------------
// Causal flash attention. Inputs pre-rounded (Q pre-scaled). cp.async K/Q,
// register-transpose V, named 64-thread pair barriers for row stats.
// ---------------------------------------------------------------------------
#define PIT 68
#define TILE_U32 (64*PIT)

__global__ __launch_bounds__(256, 2) void attn_kernel()
{
    extern __shared__ unsigned smu[];
    unsigned* Qs  = smu;                  // [q][d]
    unsigned* Ks  = Qs  + TILE_U32;       // [2][key][d]
    unsigned* Vst = Ks  + 2*TILE_U32;     // [2][d][key]
    unsigned* Ps  = Vst + 2*TILE_U32;     // [q][key]
    float* redM   = (float*)(Ps + TILE_U32);   // [2][64]
    float* redS   = redM + 128;                // [2][64]

    const int qt = (int)(gridDim.x - 1 - blockIdx.x);
    const int bh = blockIdx.y;
    const int b  = bh >> 4;
    const int h  = bh & 15;

    const size_t base = (size_t)bh * SEQ * DHEAD;
    const float* Qp = g_q + base + (size_t)qt*64*DHEAD;
    const float* Kp = g_k + base;
    const float* Vp = g_v + base;

    const int t = threadIdx.x, lane = t & 31, warp = t >> 5;
    const int wm = warp >> 1, wn = warp & 1;
    const int g  = lane >> 2, tig = lane & 3;
    const int r_lo = wm*16 + g, r_hi = r_lo + 8;

    const uint32_t qs_b = s2u(Qs), ks_b = s2u(Ks), vs_b = s2u(Vst), ps_b = s2u(Ps);

    const int m_row  = wm*16 +      (lane & 15);
    const int n_row0 = wn*32 +      (lane & 15);
    const int n_row1 = wn*32 + 16 + (lane & 15);
    const int ccol   = 4 * (lane >> 4);

    // async loader indices (Q/K): row = t>>2, 4 chunks of 4 floats
    const int lrow = t >> 2, lcb = (t & 3) * 4;
    // V transpose loader: 4x4 block
    const int vr4 = (t >> 4) * 4, vc4 = (t & 15) * 4;

    // prologue: Q + K0 via cp.async, V0 manual
    #pragma unroll
    for (int j = 0; j < 4; j++) {
        cpa16(qs_b + (uint32_t)(lrow*PIT + (lcb+j)*4)*4u,
              Qp + (size_t)lrow*DHEAD + (lcb+j)*4);
        cpa16(ks_b + (uint32_t)(lrow*PIT + (lcb+j)*4)*4u,
              Kp + (size_t)lrow*DHEAD + (lcb+j)*4);
    }
    cpa_commit();
    {
        uint4 rv[4];
        #pragma unroll
        for (int i = 0; i < 4; i++)
            rv[i] = *(const uint4*)(Vp + (size_t)(vr4+i)*DHEAD + vc4);
        const unsigned* fv = (const unsigned*)rv;
        #pragma unroll
        for (int j = 0; j < 4; j++) {
            uint4 w = make_uint4(fv[0*4+j], fv[1*4+j], fv[2*4+j], fv[3*4+j]);
            *(uint4*)&Vst[(vc4+j)*PIT + vr4] = w;
        }
    }
    cpa_wait<0>();

    float m0 = -1e30f, m1 = -1e30f, l0 = 0.f, l1 = 0.f;
    float oacc[4][4];
    #pragma unroll
    for (int i = 0; i < 4; i++)
        #pragma unroll
        for (int j = 0; j < 4; j++) oacc[i][j] = 0.f;

    for (int kt = 0; kt <= qt; kt++) {
        __syncthreads();   // publish stage(cur) K/V (+Q first iter); prev PV done
        const int cur = kt & 1, nxt = cur ^ 1;
        const bool more = (kt < qt);

        // async K load for next tile into stage nxt
        if (more) {
            const float* Kn = Kp + (size_t)(kt+1)*64*DHEAD;
            #pragma unroll
            for (int j = 0; j < 4; j++)
                cpa16(ks_b + (uint32_t)nxt*(TILE_U32*4u)
                           + (uint32_t)(lrow*PIT + (lcb+j)*4)*4u,
                      Kn + (size_t)lrow*DHEAD + (lcb+j)*4);
        }
        cpa_commit();
        // V prefetch (raw bits; already rounded)
        uint4 vpre[4];
        if (more) {
            const float* Vn = Vp + (size_t)(kt+1)*64*DHEAD;
            #pragma unroll
            for (int i = 0; i < 4; i++)
                vpre[i] = *(const uint4*)(Vn + (size_t)(vr4+i)*DHEAD + vc4);
        }

        const uint32_t ks_s = ks_b + (uint32_t)cur * (TILE_U32*4u);
        const uint32_t vs_s = vs_b + (uint32_t)cur * (TILE_U32*4u);

        // S = Q * K^T
        float sacc[4][4];
        #pragma unroll
        for (int i = 0; i < 4; i++)
            #pragma unroll
            for (int j = 0; j < 4; j++) sacc[i][j] = 0.f;

        #pragma unroll
        for (int s = 0; s < 8; s++) {
            const uint32_t cb = (uint32_t)(s*8 + ccol) * 4u;
            unsigned af[4], bf[2][4];
            ldsm4(af,    qs_b + (uint32_t)m_row*(PIT*4) + cb);
            ldsm4(bf[0], ks_s + (uint32_t)n_row0*(PIT*4) + cb);
            ldsm4(bf[1], ks_s + (uint32_t)n_row1*(PIT*4) + cb);
            #pragma unroll
            for (int nt = 0; nt < 4; nt++) {
                unsigned b2[2] = { bf[nt>>1][nt&1], bf[nt>>1][(nt&1)|2] };
                mma_tf32(sacc[nt], af, b2);
            }
        }

        // causal mask on diagonal tile (reference uses -1e5)
        if (kt == qt) {
            #pragma unroll
            for (int nt = 0; nt < 4; nt++) {
                const int c = wn*32 + nt*8 + 2*tig;
                if (c     > r_lo) sacc[nt][0] = -100000.0f;
                if (c + 1 > r_lo) sacc[nt][1] = -100000.0f;
                if (c     > r_hi) sacc[nt][2] = -100000.0f;
                if (c + 1 > r_hi) sacc[nt][3] = -100000.0f;
            }
        }

        // row max: shfl partial + pair exchange (64-thread named barrier)
        float pm0 = -1e30f, pm1 = -1e30f;
        #pragma unroll
        for (int nt = 0; nt < 4; nt++) {
            pm0 = fmaxf(pm0, fmaxf(sacc[nt][0], sacc[nt][1]));
            pm1 = fmaxf(pm1, fmaxf(sacc[nt][2], sacc[nt][3]));
        }
        pm0 = fmaxf(pm0, __shfl_xor_sync(0xffffffffu, pm0, 1));
        pm0 = fmaxf(pm0, __shfl_xor_sync(0xffffffffu, pm0, 2));
        pm1 = fmaxf(pm1, __shfl_xor_sync(0xffffffffu, pm1, 1));
        pm1 = fmaxf(pm1, __shfl_xor_sync(0xffffffffu, pm1, 2));
        if (tig == 0) { redM[wn*64 + r_lo] = pm0; redM[wn*64 + r_hi] = pm1; }
        asm volatile("bar.sync %0, 64;" :: "r"(1 + wm) : "memory");
        pm0 = fmaxf(pm0, redM[(wn^1)*64 + r_lo]);
        pm1 = fmaxf(pm1, redM[(wn^1)*64 + r_hi]);

        const float mn0 = fmaxf(m0, pm0), mn1 = fmaxf(m1, pm1);
        const float f0 = __expf(m0 - mn0), f1 = __expf(m1 - mn1);
        m0 = mn0; m1 = mn1;

        float ps0 = 0.f, ps1 = 0.f;
        #pragma unroll
        for (int nt = 0; nt < 4; nt++) {
            const float p0 = __expf(sacc[nt][0] - mn0);
            const float p1 = __expf(sacc[nt][1] - mn0);
            const float p2 = __expf(sacc[nt][2] - mn1);
            const float p3 = __expf(sacc[nt][3] - mn1);
            ps0 += p0 + p1; ps1 += p2 + p3;
            const int c = wn*32 + nt*8 + 2*tig;
            *(uint2*)&Ps[r_lo*PIT + c] = make_uint2(f2tf(p0), f2tf(p1));
            *(uint2*)&Ps[r_hi*PIT + c] = make_uint2(f2tf(p2), f2tf(p3));
            oacc[nt][0] *= f0; oacc[nt][1] *= f0;
            oacc[nt][2] *= f1; oacc[nt][3] *= f1;
        }
        ps0 += __shfl_xor_sync(0xffffffffu, ps0, 1);
        ps0 += __shfl_xor_sync(0xffffffffu, ps0, 2);
        ps1 += __shfl_xor_sync(0xffffffffu, ps1, 1);
        ps1 += __shfl_xor_sync(0xffffffffu, ps1, 2);
        if (tig == 0) { redS[wn*64 + r_lo] = ps0; redS[wn*64 + r_hi] = ps1; }
        asm volatile("bar.sync %0, 64;" :: "r"(1 + wm) : "memory");  // also orders Ps
        ps0 += redS[(wn^1)*64 + r_lo];
        ps1 += redS[(wn^1)*64 + r_hi];
        l0 = l0*f0 + ps0;
        l1 = l1*f1 + ps1;

        // stage next V (raw bit transpose) into stage nxt
        if (more) {
            unsigned* Vn = Vst + nxt*TILE_U32;
            const unsigned* fv = (const unsigned*)vpre;
            #pragma unroll
            for (int j = 0; j < 4; j++) {
                uint4 w = make_uint4(fv[0*4+j], fv[1*4+j], fv[2*4+j], fv[3*4+j]);
                *(uint4*)&Vn[(vc4+j)*PIT + vr4] = w;
            }
        }

        // O += P * V
        #pragma unroll
        for (int s = 0; s < 8; s++) {
            const uint32_t cb = (uint32_t)(s*8 + ccol) * 4u;
            unsigned af[4], bf[2][4];
            ldsm4(af,    ps_b + (uint32_t)m_row*(PIT*4) + cb);
            ldsm4(bf[0], vs_s + (uint32_t)n_row0*(PIT*4) + cb);
            ldsm4(bf[1], vs_s + (uint32_t)n_row1*(PIT*4) + cb);
            #pragma unroll
            for (int nt = 0; nt < 4; nt++) {
                unsigned b2[2] = { bf[nt>>1][nt&1], bf[nt>>1][(nt&1)|2] };
                mma_tf32(oacc[nt], af, b2);
            }
        }
        cpa_wait<0>();   // K(kt+1) landed before next loop-top sync
    }

    // normalize + write rounded (feeds oproj A operand)
    const float inv0 = 1.0f / l0, inv1 = 1.0f / l1;
    float* outp = g_att + ((size_t)b*SEQ + (size_t)qt*64)*DMODEL + h*DHEAD;
    #pragma unroll
    for (int nt = 0; nt < 4; nt++) {
        const int c = wn*32 + nt*8 + 2*tig;
        *(float2*)(outp + (size_t)r_lo*DMODEL + c) =
            make_float2(rtf(oacc[nt][0]*inv0), rtf(oacc[nt][1]*inv0));
        *(float2*)(outp + (size_t)r_hi*DMODEL + c) =
            make_float2(rtf(oacc[nt][2]*inv1), rtf(oacc[nt][3]*inv1));
    }
}

extern "C" void kernel_launch(void* const* d_in, const int* in_sizes, int n_in,
                              void* d_out, int out_size)
{
    const float* x  = (const float*)d_in[0];
    const float* Qw = (const float*)d_in[1];
    const float* Qb = (const float*)d_in[2];
    const float* Kw = (const float*)d_in[3];
    const float* Kb = (const float*)d_in[4];
    const float* Vw = (const float*)d_in[5];
    const float* Vb = (const float*)d_in[6];
    const float* Ow = (const float*)d_in[7];
    const float* Ob = (const float*)d_in[8];
    float* out = (float*)d_out;

    float* d_gwq; cudaGetSymbolAddress((void**)&d_gwq, g_wq);
    float* d_gwk; cudaGetSymbolAddress((void**)&d_gwk, g_wk);
    float* d_gwv; cudaGetSymbolAddress((void**)&d_gwv, g_wv);
    float* d_gwo; cudaGetSymbolAddress((void**)&d_gwo, g_wo);

    // pre-round / pre-transpose passes
    preround_x_kernel<<<2048, 256>>>(x);
    trw_kernel<<<dim3(2, 32, NH), dim3(32, 8)>>>(Qw, d_gwq, DMODEL, DHEAD);
    trw_kernel<<<dim3(2, 32, NH), dim3(32, 8)>>>(Kw, d_gwk, DMODEL, DHEAD);
    trw_kernel<<<dim3(2, 32, NH), dim3(32, 8)>>>(Vw, d_gwv, DMODEL, DHEAD);
    trw_kernel<<<dim3(32, 32, 1), dim3(32, 8)>>>(Ow, d_gwo, DMODEL, DMODEL);

    cudaFuncSetAttribute(qkv_kernel,
                         cudaFuncAttributeMaxDynamicSharedMemorySize, GEMM_SMEM);
    cudaFuncSetAttribute(oproj_kernel,
                         cudaFuncAttributeMaxDynamicSharedMemorySize, GEMM_SMEM);

    // QKV projection: 64 m-tiles x 48 (proj,head)
    qkv_kernel<<<dim3(64, 48), 256, GEMM_SMEM>>>(Qb, Kb, Vb);

    // Flash attention: 32 q-tiles x 64 (b,h)
    const int attn_smem = 6*TILE_U32*4 + 2*128*4;  // 105472 B
    cudaFuncSetAttribute(attn_kernel,
                         cudaFuncAttributeMaxDynamicSharedMemorySize, attn_smem);
    attn_kernel<<<dim3(32, 64), 256, attn_smem>>>();

    // Output projection: 64 m-tiles x 16 n-tiles
    oproj_kernel<<<dim3(64, 16), 256, GEMM_SMEM>>>(Ob, out);
}

// round 10
// speedup vs baseline: 1.4539x; 1.4539x over previous
#include <cuda_runtime.h>
#include <cuda_fp16.h>
#include <stdint.h>

#define BATCH 4
#define SEQ   2048
#define NH    16
#define DHEAD 64
#define DMODEL 1024

// Scratch (allocation-free rule: __device__ globals)
__device__ __half g_xh [(size_t)BATCH*SEQ*DMODEL];          // fp16 x
__device__ __half g_wqh[(size_t)NH*DHEAD*DMODEL];           // [h][d][m]
__device__ __half g_wkh[(size_t)NH*DHEAD*DMODEL];
__device__ __half g_wvh[(size_t)NH*DHEAD*DMODEL];
__device__ __half g_woh[(size_t)DMODEL*DMODEL];             // [n][k]
__device__ __half g_q  [(size_t)BATCH*NH*SEQ*DHEAD];        // [bh][s][d] (pre-scaled)
__device__ __half g_k  [(size_t)BATCH*NH*SEQ*DHEAD];
__device__ __half g_v  [(size_t)BATCH*NH*SEQ*DHEAD];
__device__ __half g_vt [(size_t)BATCH*NH*DHEAD*SEQ];        // [bh][d][s]
__device__ __half g_att[(size_t)BATCH*SEQ*DMODEL];          // fp16 attention out

__device__ __forceinline__ uint32_t s2u(const void* p){
    return (uint32_t)__cvta_generic_to_shared(p);
}
__device__ __forceinline__ void ldsm4(unsigned r[4], uint32_t addr){
    asm volatile("ldmatrix.sync.aligned.m8n8.x4.shared.b16 {%0,%1,%2,%3}, [%4];"
        : "=r"(r[0]), "=r"(r[1]), "=r"(r[2]), "=r"(r[3]) : "r"(addr));
}
__device__ __forceinline__ void mma_f16(float* d, const unsigned* a, const unsigned* b){
    asm volatile(
        "mma.sync.aligned.m16n8k16.row.col.f32.f16.f16.f32 "
        "{%0,%1,%2,%3},{%4,%5,%6,%7},{%8,%9},{%0,%1,%2,%3};\n"
        : "+f"(d[0]), "+f"(d[1]), "+f"(d[2]), "+f"(d[3])
        : "r"(a[0]), "r"(a[1]), "r"(a[2]), "r"(a[3]), "r"(b[0]), "r"(b[1]));
}
__device__ __forceinline__ void cpa16(uint32_t dst, const void* src){
    asm volatile("cp.async.cg.shared.global [%0], [%1], 16;\n" :: "r"(dst), "l"(src));
}
__device__ __forceinline__ void cpa_commit(){
    asm volatile("cp.async.commit_group;\n" ::: "memory");
}
template<int N>
__device__ __forceinline__ void cpa_wait(){
    asm volatile("cp.async.wait_group %0;\n" :: "n"(N) : "memory");
}

// canonical ldmatrix x4 fragment address (16-row group, SW128 swizzled rows of
// 8 16B chunks). row0 multiple of 16; kc = k-chunk base (k0/8).
__device__ __forceinline__ uint32_t frag_addr(uint32_t base, int row0, int kc, int lane){
    const int row = row0 + (lane & 7) + ((lane >> 3) & 1) * 8;
    const int cc  = kc + (lane >> 4);
    return base + (uint32_t)row*128u + (uint32_t)((cc ^ (lane & 7)) * 16);
}

// ---------------------------------------------------------------------------
// Prework: x -> fp16
// ---------------------------------------------------------------------------
__global__ void cvt_x_kernel(const float* __restrict__ x)
{
    const size_t n4 = (size_t)BATCH*SEQ*DMODEL/4;
    for (size_t i = blockIdx.x*blockDim.x + threadIdx.x; i < n4;
         i += (size_t)gridDim.x*blockDim.x) {
        float4 v = ((const float4*)x)[i];
        __half2 lo = __floats2half2_rn(v.x, v.y);
        __half2 hi = __floats2half2_rn(v.z, v.w);
        ((uint2*)g_xh)[i] = make_uint2(*(unsigned*)&lo, *(unsigned*)&hi);
    }
}

// ---------------------------------------------------------------------------
// Prework: transpose fp32 [z][rows][cols] -> fp16 [z][cols][rows]
// ---------------------------------------------------------------------------
__global__ void trw_kernel(const float* __restrict__ in, __half* __restrict__ out,
                           int rows, int cols)
{
    __shared__ float tile[32][33];
    const size_t iboff = (size_t)blockIdx.z * rows * cols;
    const int c0 = blockIdx.x*32, r0 = blockIdx.y*32;
    const int tx = threadIdx.x, ty = threadIdx.y;   // 32 x 8
    #pragma unroll
    for (int i = 0; i < 32; i += 8)
        tile[ty+i][tx] = in[iboff + (size_t)(r0+ty+i)*cols + c0+tx];
    __syncthreads();
    #pragma unroll
    for (int i = 0; i < 32; i += 8)
        out[iboff + (size_t)(c0+ty+i)*rows + r0+tx] = __float2half_rn(tile[tx][ty+i]);
}

// ---------------------------------------------------------------------------
// Prework: V transpose fp16 [bh][s][d] -> [bh][d][s]
// ---------------------------------------------------------------------------
__global__ void trv_kernel()
{
    __shared__ __half tile[32][33];
    const size_t bo = (size_t)blockIdx.z * SEQ * DHEAD;
    const size_t bt = (size_t)blockIdx.z * DHEAD * SEQ;
    const int s0 = blockIdx.x*32, d0 = blockIdx.y*32;
    const int tx = threadIdx.x, ty = threadIdx.y;   // 32 x 8
    #pragma unroll
    for (int i = 0; i < 32; i += 8)
        tile[ty+i][tx] = g_v[bo + (size_t)(s0+ty+i)*DHEAD + d0+tx];
    __syncthreads();
    #pragma unroll
    for (int i = 0; i < 32; i += 8)
        g_vt[bt + (size_t)(d0+ty+i)*SEQ + s0+tx] = tile[tx][ty+i];
}

// ---------------------------------------------------------------------------
// fp16 GEMM core: C[128 x 64] = A[128 x 1024] * B[64 x 1024]^T (+bias)
// 256 threads, 8 warps (4m x 2n), warp tile 32x32, BK=64 (128B fp16 rows).
// 2-stage cp.async, SW128 swizzle, canonical ldmatrix fragments.
// ---------------------------------------------------------------------------
#define GSTG 24576   // bytes per stage: A 16KB + B 8KB
#define GEMM_SMEM (2*GSTG)

struct GemmAcc { float a[2][4][4]; };

__device__ __forceinline__ void gemm_mainloop(
    const __half* __restrict__ A, const __half* __restrict__ Bt,
    GemmAcc& acc)
{
    extern __shared__ unsigned char sm[];
    const uint32_t sb = s2u(sm);

    const int t = threadIdx.x, lane = t & 31, warp = t >> 5;
    const int wm = warp >> 1, wn = warp & 1;

    // loader chunk maps
    uint32_t a_dst[4]; const __half* a_src[4];
    #pragma unroll
    for (int j = 0; j < 4; j++) {
        const int id = t*4 + j, r = id >> 3, c = id & 7;
        a_dst[j] = sb + (uint32_t)(r*128 + ((c ^ (r&7))*16));
        a_src[j] = A + (size_t)r*DMODEL + c*8;
    }
    uint32_t b_dst[2]; const __half* b_src[2];
    #pragma unroll
    for (int j = 0; j < 2; j++) {
        const int id = t*2 + j, r = id >> 3, c = id & 7;
        b_dst[j] = sb + 16384u + (uint32_t)(r*128 + ((c ^ (r&7))*16));
        b_src[j] = Bt + (size_t)r*DMODEL + c*8;
    }

    // prologue: stage 0
    #pragma unroll
    for (int j = 0; j < 4; j++) cpa16(a_dst[j], a_src[j]);
    #pragma unroll
    for (int j = 0; j < 2; j++) cpa16(b_dst[j], b_src[j]);
    cpa_commit();

    const int iters = DMODEL / 64;   // 16
    for (int it = 0; it < iters; it++) {
        if (it + 1 < iters) {
            const uint32_t off = (uint32_t)((it+1) & 1) * GSTG;
            #pragma unroll
            for (int j = 0; j < 4; j++) cpa16(a_dst[j] + off, a_src[j] + (it+1)*64);
            #pragma unroll
            for (int j = 0; j < 2; j++) cpa16(b_dst[j] + off, b_src[j] + (it+1)*64);
            cpa_commit();
            cpa_wait<1>();
        } else {
            cpa_wait<0>();
        }
        __syncthreads();

        const uint32_t as = sb + (uint32_t)(it & 1) * GSTG;
        const uint32_t bs = as + 16384u;
        #pragma unroll
        for (int s = 0; s < 4; s++) {
            const int kc = s*2;
            unsigned a0[4], a1[4], bf0[4], bf1[4];
            ldsm4(a0,  frag_addr(as, wm*32,      kc, lane));
            ldsm4(a1,  frag_addr(as, wm*32 + 16, kc, lane));
            ldsm4(bf0, frag_addr(bs, wn*32,      kc, lane));
            ldsm4(bf1, frag_addr(bs, wn*32 + 16, kc, lane));
            #pragma unroll
            for (int nt = 0; nt < 4; nt++) {
                const unsigned* bsrc = (nt < 2) ? bf0 : bf1;
                unsigned bb[2] = { bsrc[nt & 1], bsrc[(nt & 1) + 2] };
                mma_f16(acc.a[0][nt], a0, bb);
                mma_f16(acc.a[1][nt], a1, bb);
            }
        }
        __syncthreads();
    }
}

// ---------------------------------------------------------------------------
// QKV projection (fp16 out; Q pre-scaled by 1/8)
// ---------------------------------------------------------------------------
__global__ __launch_bounds__(256, 2) void qkv_kernel(
    const float* __restrict__ Qb, const float* __restrict__ Kb,
    const float* __restrict__ Vb)
{
    const int proj = blockIdx.y >> 4;
    const int h    = blockIdx.y & 15;
    const int rbase = blockIdx.x * 128;
    const int b     = rbase >> 11;
    const int srow  = rbase & 2047;

    const __half* W; const float* bias; __half* out;
    if (proj == 0)      { W = g_wqh; bias = Qb; out = g_q; }
    else if (proj == 1) { W = g_wkh; bias = Kb; out = g_k; }
    else                { W = g_wvh; bias = Vb; out = g_v; }

    GemmAcc acc;
    #pragma unroll
    for (int i = 0; i < 2; i++)
        #pragma unroll
        for (int j = 0; j < 4; j++)
            #pragma unroll
            for (int c = 0; c < 4; c++) acc.a[i][j][c] = 0.f;

    gemm_mainloop(g_xh + (size_t)rbase*DMODEL,
                  W + (size_t)h*DHEAD*DMODEL, acc);

    const int t = threadIdx.x, lane = t & 31, warp = t >> 5;
    const int wm = warp >> 1, wn = warp & 1;
    const int g = lane >> 2, tig = lane & 3;
    const float sc = (proj == 0) ? 0.125f : 1.0f;

    __half* outp = out + (((size_t)(b*NH + h))*SEQ + srow)*DHEAD;
    #pragma unroll
    for (int mt = 0; mt < 2; mt++) {
        #pragma unroll
        for (int nt = 0; nt < 4; nt++) {
            const int row = wm*32 + mt*16 + g;
            const int col = wn*32 + nt*8 + 2*tig;
            const float b0 = bias[h*DHEAD + col], b1 = bias[h*DHEAD + col + 1];
            __half2 lo = __floats2half2_rn((acc.a[mt][nt][0] + b0)*sc,
                                           (acc.a[mt][nt][1] + b1)*sc);
            __half2 hi = __floats2half2_rn((acc.a[mt][nt][2] + b0)*sc,
                                           (acc.a[mt][nt][3] + b1)*sc);
            *(__half2*)(outp + (size_t)row*DHEAD + col)     = lo;
            *(__half2*)(outp + (size_t)(row+8)*DHEAD + col) = hi;
        }
    }
}

// ---------------------------------------------------------------------------
// Output projection (fp32 out + bias)
// ---------------------------------------------------------------------------
__global__ __launch_bounds__(256, 2) void oproj_kernel(
    const float* __restrict__ Ob, float* __restrict__ out)
{
    const int rbase = blockIdx.x * 128;
    const int nbase = blockIdx.y * 64;

    GemmAcc acc;
    #pragma unroll
    for (int i = 0; i < 2; i++)
        #pragma unroll
        for (int j = 0; j < 4; j++)
            #pragma unroll
            for (int c = 0; c < 4; c++) acc.a[i][j][c] = 0.f;

    gemm_mainloop(g_att + (size_t)rbase*DMODEL,
                  g_woh + (size_t)nbase*DMODEL, acc);

    const int t = threadIdx.x, lane = t & 31, warp = t >> 5;
    const int wm = warp >> 1, wn = warp & 1;
    const int g = lane >> 2, tig = lane & 3;

    #pragma unroll
    for (int mt = 0; mt < 2; mt++) {
        #pragma unroll
        for (int nt = 0; nt < 4; nt++) {
            const int row = rbase + wm*32 + mt*16 + g;
            const int col = nbase + wn*32 + nt*8 + 2*tig;
            const float b0 = Ob[col], b1 = Ob[col+1];
            *(float2*)(out + (size_t)row*DMODEL + col) =
                make_float2(acc.a[mt][nt][0] + b0, acc.a[mt][nt][1] + b1);
            *(float2*)(out + (size_t)(row+8)*DMODEL + col) =
                make_float2(acc.a[mt][nt][2] + b0, acc.a[mt][nt][3] + b1);
        }
    }
}

// ---------------------------------------------------------------------------
// Causal flash attention, fp16 mma. Block = (64 q rows, one (b,h)).
// 8 warps (4m x 2n). All tiles 64x64 fp16 = 8KB, SW128 swizzle, cp.async.
// ---------------------------------------------------------------------------
#define QS_OFF  0u
#define KS_OFF  8192u
#define VS_OFF  24576u
#define PS_OFF  40960u
#define RED_OFF 49152u
#define ATTN_SMEM (49152 + 1024)

__global__ __launch_bounds__(256, 2) void attn_kernel()
{
    extern __shared__ unsigned char sm[];
    const uint32_t sb = s2u(sm);
    float* redM = (float*)(sm + RED_OFF);          // [2][64]
    float* redS = (float*)(sm + RED_OFF + 512);    // [2][64]

    const int qt = (int)(gridDim.x - 1 - blockIdx.x);  // big tiles first
    const int bh = blockIdx.y;
    const int b  = bh >> 4;
    const int h  = bh & 15;

    const __half* Qp = g_q  + (size_t)bh*SEQ*DHEAD + (size_t)qt*64*DHEAD;
    const __half* Kp = g_k  + (size_t)bh*SEQ*DHEAD;
    const __half* Vt = g_vt + (size_t)bh*DHEAD*SEQ;

    const int t = threadIdx.x, lane = t & 31, warp = t >> 5;
    const int wm = warp >> 1, wn = warp & 1;
    const int g  = lane >> 2, tig = lane & 3;
    const int r_lo = wm*16 + g, r_hi = r_lo + 8;

    // staging chunk map: 512 chunks per tile, 2 per thread
    int ld_r[2], ld_c[2]; uint32_t ld_dst[2];
    #pragma unroll
    for (int j = 0; j < 2; j++) {
        const int id = t*2 + j;
        ld_r[j] = id >> 3; ld_c[j] = id & 7;
        ld_dst[j] = (uint32_t)(ld_r[j]*128 + ((ld_c[j] ^ (ld_r[j]&7))*16));
    }

    // prologue: Q + K0 + V0
    #pragma unroll
    for (int j = 0; j < 2; j++) {
        cpa16(sb + QS_OFF + ld_dst[j], Qp + (size_t)ld_r[j]*DHEAD + ld_c[j]*8);
        cpa16(sb + KS_OFF + ld_dst[j], Kp + (size_t)ld_r[j]*DHEAD + ld_c[j]*8);
        cpa16(sb + VS_OFF + ld_dst[j], Vt + (size_t)ld_r[j]*SEQ + ld_c[j]*8);
    }
    cpa_commit();
    cpa_wait<0>();

    float m0 = -1e30f, m1 = -1e30f, l0 = 0.f, l1 = 0.f;
    float oacc[4][4];
    #pragma unroll
    for (int i = 0; i < 4; i++)
        #pragma unroll
        for (int j = 0; j < 4; j++) oacc[i][j] = 0.f;

    for (int kt = 0; kt <= qt; kt++) {
        __syncthreads();   // publish staged tiles; prev PV done
        const int cur = kt & 1, nxt = cur ^ 1;
        const bool more = (kt < qt);

        // async loads for next K/V tile
        if (more) {
            const __half* Kn = Kp + (size_t)(kt+1)*64*DHEAD;
            #pragma unroll
            for (int j = 0; j < 2; j++) {
                cpa16(sb + KS_OFF + (uint32_t)nxt*8192u + ld_dst[j],
                      Kn + (size_t)ld_r[j]*DHEAD + ld_c[j]*8);
                cpa16(sb + VS_OFF + (uint32_t)nxt*8192u + ld_dst[j],
                      Vt + (size_t)ld_r[j]*SEQ + (kt+1)*64 + ld_c[j]*8);
            }
        }
        cpa_commit();

        const uint32_t ks = sb + KS_OFF + (uint32_t)cur*8192u;
        const uint32_t vs = sb + VS_OFF + (uint32_t)cur*8192u;

        // S = Q * K^T  (m=64, n=64 keys, k=64 d)
        float sacc[4][4];
        #pragma unroll
        for (int i = 0; i < 4; i++)
            #pragma unroll
            for (int j = 0; j < 4; j++) sacc[i][j] = 0.f;

        #pragma unroll
        for (int s = 0; s < 4; s++) {
            const int kc = s*2;
            unsigned af[4], bf0[4], bf1[4];
            ldsm4(af,  frag_addr(sb + QS_OFF, wm*16, kc, lane));
            ldsm4(bf0, frag_addr(ks, wn*32,      kc, lane));
            ldsm4(bf1, frag_addr(ks, wn*32 + 16, kc, lane));
            #pragma unroll
            for (int nt = 0; nt < 4; nt++) {
                const unsigned* bsrc = (nt < 2) ? bf0 : bf1;
                unsigned bb[2] = { bsrc[nt & 1], bsrc[(nt & 1) + 2] };
                mma_f16(sacc[nt], af, bb);
            }
        }

        // causal mask on diagonal tile (reference uses -1e5)
        if (kt == qt) {
            #pragma unroll
            for (int nt = 0; nt < 4; nt++) {
                const int c = wn*32 + nt*8 + 2*tig;
                if (c     > r_lo) sacc[nt][0] = -100000.0f;
                if (c + 1 > r_lo) sacc[nt][1] = -100000.0f;
                if (c     > r_hi) sacc[nt][2] = -100000.0f;
                if (c + 1 > r_hi) sacc[nt][3] = -100000.0f;
            }
        }

        // row max: shfl partial + warp-pair exchange
        float pm0 = -1e30f, pm1 = -1e30f;
        #pragma unroll
        for (int nt = 0; nt < 4; nt++) {
            pm0 = fmaxf(pm0, fmaxf(sacc[nt][0], sacc[nt][1]));
            pm1 = fmaxf(pm1, fmaxf(sacc[nt][2], sacc[nt][3]));
        }
        pm0 = fmaxf(pm0, __shfl_xor_sync(0xffffffffu, pm0, 1));
        pm0 = fmaxf(pm0, __shfl_xor_sync(0xffffffffu, pm0, 2));
        pm1 = fmaxf(pm1, __shfl_xor_sync(0xffffffffu, pm1, 1));
        pm1 = fmaxf(pm1, __shfl_xor_sync(0xffffffffu, pm1, 2));
        if (tig == 0) { redM[wn*64 + r_lo] = pm0; redM[wn*64 + r_hi] = pm1; }
        asm volatile("bar.sync %0, 64;" :: "r"(1 + wm) : "memory");
        pm0 = fmaxf(pm0, redM[(wn^1)*64 + r_lo]);
        pm1 = fmaxf(pm1, redM[(wn^1)*64 + r_hi]);

        const float mn0 = fmaxf(m0, pm0), mn1 = fmaxf(m1, pm1);
        const float f0 = __expf(m0 - mn0), f1 = __expf(m1 - mn1);
        m0 = mn0; m1 = mn1;

        float ps0 = 0.f, ps1 = 0.f;
        #pragma unroll
        for (int nt = 0; nt < 4; nt++) {
            const float p0 = __expf(sacc[nt][0] - mn0);
            const float p1 = __expf(sacc[nt][1] - mn0);
            const float p2 = __expf(sacc[nt][2] - mn1);
            const float p3 = __expf(sacc[nt][3] - mn1);
            ps0 += p0 + p1; ps1 += p2 + p3;
            // store P as half2 into swizzled Ps
            const int cc = wn*4 + nt;       // chunk col (c>>3)
            const int wo = tig*4;           // byte offset within chunk (2tig halves)
            *(__half2*)(sm + PS_OFF + r_lo*128 + ((cc ^ (r_lo&7))*16) + wo) =
                __floats2half2_rn(p0, p1);
            *(__half2*)(sm + PS_OFF + r_hi*128 + ((cc ^ (r_hi&7))*16) + wo) =
                __floats2half2_rn(p2, p3);
            oacc[nt][0] *= f0; oacc[nt][1] *= f0;
            oacc[nt][2] *= f1; oacc[nt][3] *= f1;
        }
        ps0 += __shfl_xor_sync(0xffffffffu, ps0, 1);
        ps0 += __shfl_xor_sync(0xffffffffu, ps0, 2);
        ps1 += __shfl_xor_sync(0xffffffffu, ps1, 1);
        ps1 += __shfl_xor_sync(0xffffffffu, ps1, 2);
        if (tig == 0) { redS[wn*64 + r_lo] = ps0; redS[wn*64 + r_hi] = ps1; }
        asm volatile("bar.sync %0, 64;" :: "r"(1 + wm) : "memory");  // Ps rows ready
        ps0 += redS[(wn^1)*64 + r_lo];
        ps1 += redS[(wn^1)*64 + r_hi];
        l0 = l0*f0 + ps0;
        l1 = l1*f1 + ps1;

        // O += P * V   (A = Ps[q][key], B = Vt[d][key])
        #pragma unroll
        for (int s = 0; s < 4; s++) {
            const int kc = s*2;
            unsigned af[4], bf0[4], bf1[4];
            ldsm4(af,  frag_addr(sb + PS_OFF, wm*16, kc, lane));
            ldsm4(bf0, frag_addr(vs, wn*32,      kc, lane));
            ldsm4(bf1, frag_addr(vs, wn*32 + 16, kc, lane));
            #pragma unroll
            for (int nt = 0; nt < 4; nt++) {
                const unsigned* bsrc = (nt < 2) ? bf0 : bf1;
                unsigned bb[2] = { bsrc[nt & 1], bsrc[(nt & 1) + 2] };
                mma_f16(oacc[nt], af, bb);
            }
        }
        cpa_wait<0>();   // next K/V landed before loop-top sync
    }

    // normalize + write g_att (fp16)
    const float inv0 = 1.0f / l0, inv1 = 1.0f / l1;
    __half* outp = g_att + ((size_t)b*SEQ + (size_t)qt*64)*DMODEL + h*DHEAD;
    #pragma unroll
    for (int nt = 0; nt < 4; nt++) {
        const int c = wn*32 + nt*8 + 2*tig;
        *(__half2*)(outp + (size_t)r_lo*DMODEL + c) =
            __floats2half2_rn(oacc[nt][0]*inv0, oacc[nt][1]*inv0);
        *(__half2*)(outp + (size_t)r_hi*DMODEL + c) =
            __floats2half2_rn(oacc[nt][2]*inv1, oacc[nt][3]*inv1);
    }
}

extern "C" void kernel_launch(void* const* d_in, const int* in_sizes, int n_in,
                              void* d_out, int out_size)
{
    const float* x  = (const float*)d_in[0];
    const float* Qw = (const float*)d_in[1];
    const float* Qb = (const float*)d_in[2];
    const float* Kw = (const float*)d_in[3];
    const float* Kb = (const float*)d_in[4];
    const float* Vw = (const float*)d_in[5];
    const float* Vb = (const float*)d_in[6];
    const float* Ow = (const float*)d_in[7];
    const float* Ob = (const float*)d_in[8];
    float* out = (float*)d_out;

    __half* d_wq; cudaGetSymbolAddress((void**)&d_wq, g_wqh);
    __half* d_wk; cudaGetSymbolAddress((void**)&d_wk, g_wkh);
    __half* d_wv; cudaGetSymbolAddress((void**)&d_wv, g_wvh);
    __half* d_wo; cudaGetSymbolAddress((void**)&d_wo, g_woh);

    // prework: fp16 conversions + weight transposes
    cvt_x_kernel<<<2048, 256>>>(x);
    trw_kernel<<<dim3(2, 32, NH), dim3(32, 8)>>>(Qw, d_wq, DMODEL, DHEAD);
    trw_kernel<<<dim3(2, 32, NH), dim3(32, 8)>>>(Kw, d_wk, DMODEL, DHEAD);
    trw_kernel<<<dim3(2, 32, NH), dim3(32, 8)>>>(Vw, d_wv, DMODEL, DHEAD);
    trw_kernel<<<dim3(32, 32, 1), dim3(32, 8)>>>(Ow, d_wo, DMODEL, DMODEL);

    cudaFuncSetAttribute(qkv_kernel,
                         cudaFuncAttributeMaxDynamicSharedMemorySize, GEMM_SMEM);
    cudaFuncSetAttribute(oproj_kernel,
                         cudaFuncAttributeMaxDynamicSharedMemorySize, GEMM_SMEM);
    cudaFuncSetAttribute(attn_kernel,
                         cudaFuncAttributeMaxDynamicSharedMemorySize, ATTN_SMEM);

    // QKV projection: 64 m-tiles x 48 (proj,head)
    qkv_kernel<<<dim3(64, 48), 256, GEMM_SMEM>>>(Qb, Kb, Vb);

    // V transpose for attention B-operand
    trv_kernel<<<dim3(64, 2, BATCH*NH), dim3(32, 8)>>>();

    // Flash attention: 32 q-tiles x 64 (b,h)
    attn_kernel<<<dim3(32, 64), 256, ATTN_SMEM>>>();

    // Output projection: 64 m-tiles x 16 n-tiles
    oproj_kernel<<<dim3(64, 16), 256, GEMM_SMEM>>>(Ob, out);
}

// round 11
// speedup vs baseline: 2.4294x; 1.6710x over previous
#include <cuda_runtime.h>
#include <cuda_fp16.h>
#include <stdint.h>

#define BATCH 4
#define SEQ   2048
#define NH    16
#define DHEAD 64
#define DMODEL 1024

// Scratch (allocation-free rule: __device__ globals)
__device__ __half g_xh [(size_t)BATCH*SEQ*DMODEL];          // fp16 x
__device__ __half g_wqh[(size_t)NH*DHEAD*DMODEL];           // [h][d][m]
__device__ __half g_wkh[(size_t)NH*DHEAD*DMODEL];
__device__ __half g_wvh[(size_t)NH*DHEAD*DMODEL];
__device__ __half g_woh[(size_t)DMODEL*DMODEL];             // [n][k]
__device__ __half g_q  [(size_t)BATCH*NH*SEQ*DHEAD];        // [bh][s][d] (pre-scaled)
__device__ __half g_k  [(size_t)BATCH*NH*SEQ*DHEAD];
__device__ __half g_v  [(size_t)BATCH*NH*SEQ*DHEAD];
__device__ __half g_vt [(size_t)BATCH*NH*DHEAD*SEQ];        // [bh][d][s]
__device__ __half g_att[(size_t)BATCH*SEQ*DMODEL];          // fp16 attention out

__device__ __forceinline__ uint32_t s2u(const void* p){
    return (uint32_t)__cvta_generic_to_shared(p);
}
__device__ __forceinline__ void ldsm4(unsigned r[4], uint32_t addr){
    asm volatile("ldmatrix.sync.aligned.m8n8.x4.shared.b16 {%0,%1,%2,%3}, [%4];"
        : "=r"(r[0]), "=r"(r[1]), "=r"(r[2]), "=r"(r[3]) : "r"(addr));
}
__device__ __forceinline__ void mma_f16(float* d, const unsigned* a, const unsigned* b){
    asm volatile(
        "mma.sync.aligned.m16n8k16.row.col.f32.f16.f16.f32 "
        "{%0,%1,%2,%3},{%4,%5,%6,%7},{%8,%9},{%0,%1,%2,%3};\n"
        : "+f"(d[0]), "+f"(d[1]), "+f"(d[2]), "+f"(d[3])
        : "r"(a[0]), "r"(a[1]), "r"(a[2]), "r"(a[3]), "r"(b[0]), "r"(b[1]));
}
__device__ __forceinline__ void cpa16(uint32_t dst, const void* src){
    asm volatile("cp.async.cg.shared.global [%0], [%1], 16;\n" :: "r"(dst), "l"(src));
}
__device__ __forceinline__ void cpa_commit(){
    asm volatile("cp.async.commit_group;\n" ::: "memory");
}
template<int N>
__device__ __forceinline__ void cpa_wait(){
    asm volatile("cp.async.wait_group %0;\n" :: "n"(N) : "memory");
}
__device__ __forceinline__ unsigned h2u(__half2 h){ return *(unsigned*)&h; }

// ldmatrix x4 fragment address: rows of 8 16B chunks, SW128 XOR swizzle.
// row0 multiple of 16; kc = k-chunk base (k0/8).
__device__ __forceinline__ uint32_t frag_addr(uint32_t base, int row0, int kc, int lane){
    const int row = row0 + (lane & 7) + ((lane >> 3) & 1) * 8;
    const int cc  = kc + (lane >> 4);
    return base + (uint32_t)row*128u + (uint32_t)((cc ^ (lane & 7)) * 16);
}

// ---------------------------------------------------------------------------
// Prework
// ---------------------------------------------------------------------------
__global__ void cvt_x_kernel(const float* __restrict__ x)
{
    const size_t n4 = (size_t)BATCH*SEQ*DMODEL/4;
    for (size_t i = blockIdx.x*blockDim.x + threadIdx.x; i < n4;
         i += (size_t)gridDim.x*blockDim.x) {
        float4 v = ((const float4*)x)[i];
        __half2 lo = __floats2half2_rn(v.x, v.y);
        __half2 hi = __floats2half2_rn(v.z, v.w);
        ((uint2*)g_xh)[i] = make_uint2(h2u(lo), h2u(hi));
    }
}

__global__ void trw_kernel(const float* __restrict__ in, __half* __restrict__ out,
                           int rows, int cols)
{
    __shared__ float tile[32][33];
    const size_t iboff = (size_t)blockIdx.z * rows * cols;
    const int c0 = blockIdx.x*32, r0 = blockIdx.y*32;
    const int tx = threadIdx.x, ty = threadIdx.y;   // 32 x 8
    #pragma unroll
    for (int i = 0; i < 32; i += 8)
        tile[ty+i][tx] = in[iboff + (size_t)(r0+ty+i)*cols + c0+tx];
    __syncthreads();
    #pragma unroll
    for (int i = 0; i < 32; i += 8)
        out[iboff + (size_t)(c0+ty+i)*rows + r0+tx] = __float2half_rn(tile[tx][ty+i]);
}

__global__ void trv_kernel()
{
    __shared__ __half tile[32][33];
    const size_t bo = (size_t)blockIdx.z * SEQ * DHEAD;
    const size_t bt = (size_t)blockIdx.z * DHEAD * SEQ;
    const int s0 = blockIdx.x*32, d0 = blockIdx.y*32;
    const int tx = threadIdx.x, ty = threadIdx.y;   // 32 x 8
    #pragma unroll
    for (int i = 0; i < 32; i += 8)
        tile[ty+i][tx] = g_v[bo + (size_t)(s0+ty+i)*DHEAD + d0+tx];
    __syncthreads();
    #pragma unroll
    for (int i = 0; i < 32; i += 8)
        g_vt[bt + (size_t)(d0+ty+i)*SEQ + s0+tx] = tile[tx][ty+i];
}

// ---------------------------------------------------------------------------
// fp16 GEMM core: C[128 x 128] = A[128 x 1024] * B[128 x 1024]^T
// 256 threads, 8 warps (2m x 4n), warp tile 64x32, BK=64, 2-stage cp.async.
// ---------------------------------------------------------------------------
#define GSTG 32768   // bytes per stage: A 16KB + B 16KB
#define GEMM_SMEM (2*GSTG)

__device__ __forceinline__ void gemm_mainloop128(
    const __half* __restrict__ A, const __half* __restrict__ Bt,
    float acc[4][4][4])
{
    extern __shared__ unsigned char sm[];
    const uint32_t sb = s2u(sm);

    const int t = threadIdx.x, lane = t & 31, warp = t >> 5;
    const int wm = warp >> 2, wn = warp & 3;

    uint32_t a_dst[4]; const __half* a_src[4];
    uint32_t b_dst[4]; const __half* b_src[4];
    #pragma unroll
    for (int j = 0; j < 4; j++) {
        const int id = t*4 + j, r = id >> 3, c = id & 7;
        const uint32_t sw = (uint32_t)(r*128 + ((c ^ (r&7))*16));
        a_dst[j] = sb + sw;
        b_dst[j] = sb + 16384u + sw;
        a_src[j] = A  + (size_t)r*DMODEL + c*8;
        b_src[j] = Bt + (size_t)r*DMODEL + c*8;
    }

    // prologue: stage 0
    #pragma unroll
    for (int j = 0; j < 4; j++) { cpa16(a_dst[j], a_src[j]); cpa16(b_dst[j], b_src[j]); }
    cpa_commit();

    const int iters = DMODEL / 64;   // 16
    for (int it = 0; it < iters; it++) {
        if (it + 1 < iters) {
            const uint32_t off = (uint32_t)((it+1) & 1) * GSTG;
            #pragma unroll
            for (int j = 0; j < 4; j++) {
                cpa16(a_dst[j] + off, a_src[j] + (it+1)*64);
                cpa16(b_dst[j] + off, b_src[j] + (it+1)*64);
            }
            cpa_commit();
            cpa_wait<1>();
        } else {
            cpa_wait<0>();
        }
        __syncthreads();

        const uint32_t as = sb + (uint32_t)(it & 1) * GSTG;
        const uint32_t bs = as + 16384u;
        #pragma unroll
        for (int s = 0; s < 4; s++) {
            const int kc = s*2;
            unsigned af[4][4], bf0[4], bf1[4];
            #pragma unroll
            for (int mt = 0; mt < 4; mt++)
                ldsm4(af[mt], frag_addr(as, wm*64 + mt*16, kc, lane));
            ldsm4(bf0, frag_addr(bs, wn*32,      kc, lane));
            ldsm4(bf1, frag_addr(bs, wn*32 + 16, kc, lane));
            #pragma unroll
            for (int mt = 0; mt < 4; mt++)
                #pragma unroll
                for (int nt = 0; nt < 4; nt++) {
                    const unsigned* bsrc = (nt < 2) ? bf0 : bf1;
                    unsigned bb[2] = { bsrc[nt & 1], bsrc[(nt & 1) + 2] };
                    mma_f16(acc[mt][nt], af[mt], bb);
                }
        }
        __syncthreads();
    }
}

// ---------------------------------------------------------------------------
// QKV projection (fp16 out; Q pre-scaled by 1/8). Grid (64 m, 24 n-tiles).
// ---------------------------------------------------------------------------
__global__ __launch_bounds__(256, 2) void qkv_kernel(
    const float* __restrict__ Qb, const float* __restrict__ Kb,
    const float* __restrict__ Vb)
{
    const int proj = blockIdx.y >> 3;        // 0..2
    const int nb   = (blockIdx.y & 7) * 128; // col base within proj
    const int rbase = blockIdx.x * 128;
    const int b     = rbase >> 11;
    const int srow  = rbase & 2047;

    const __half* W; const float* bias; __half* out;
    if (proj == 0)      { W = g_wqh; bias = Qb; out = g_q; }
    else if (proj == 1) { W = g_wkh; bias = Kb; out = g_k; }
    else                { W = g_wvh; bias = Vb; out = g_v; }

    float acc[4][4][4];
    #pragma unroll
    for (int i = 0; i < 4; i++)
        #pragma unroll
        for (int j = 0; j < 4; j++)
            #pragma unroll
            for (int c = 0; c < 4; c++) acc[i][j][c] = 0.f;

    gemm_mainloop128(g_xh + (size_t)rbase*DMODEL, W + (size_t)nb*DMODEL, acc);

    const int t = threadIdx.x, lane = t & 31, warp = t >> 5;
    const int wm = warp >> 2, wn = warp & 3;
    const int g = lane >> 2, tig = lane & 3;
    const float sc = (proj == 0) ? 0.125f : 1.0f;

    #pragma unroll
    for (int mt = 0; mt < 4; mt++) {
        #pragma unroll
        for (int nt = 0; nt < 4; nt++) {
            const int row = wm*64 + mt*16 + g;
            const int col = nb + wn*32 + nt*8 + 2*tig;   // within proj, 0..1023
            const int head = col >> 6, d = col & 63;
            const float b0 = bias[col], b1 = bias[col+1];
            __half* outp = out + (((size_t)(b*NH + head))*SEQ + srow + row)*DHEAD + d;
            *(__half2*)outp =
                __floats2half2_rn((acc[mt][nt][0] + b0)*sc, (acc[mt][nt][1] + b1)*sc);
            *(__half2*)(outp + 8*DHEAD) =
                __floats2half2_rn((acc[mt][nt][2] + b0)*sc, (acc[mt][nt][3] + b1)*sc);
        }
    }
}

// ---------------------------------------------------------------------------
// Output projection (fp32 out + bias). Grid (64 m, 8 n-tiles).
// ---------------------------------------------------------------------------
__global__ __launch_bounds__(256, 2) void oproj_kernel(
    const float* __restrict__ Ob, float* __restrict__ out)
{
    const int rbase = blockIdx.x * 128;
    const int nbase = blockIdx.y * 128;

    float acc[4][4][4];
    #pragma unroll
    for (int i = 0; i < 4; i++)
        #pragma unroll
        for (int j = 0; j < 4; j++)
            #pragma unroll
            for (int c = 0; c < 4; c++) acc[i][j][c] = 0.f;

    gemm_mainloop128(g_att + (size_t)rbase*DMODEL, g_woh + (size_t)nbase*DMODEL, acc);

    const int t = threadIdx.x, lane = t & 31, warp = t >> 5;
    const int wm = warp >> 2, wn = warp & 3;
    const int g = lane >> 2, tig = lane & 3;

    #pragma unroll
    for (int mt = 0; mt < 4; mt++) {
        #pragma unroll
        for (int nt = 0; nt < 4; nt++) {
            const int row = rbase + wm*64 + mt*16 + g;
            const int col = nbase + wn*32 + nt*8 + 2*tig;
            const float b0 = Ob[col], b1 = Ob[col+1];
            *(float2*)(out + (size_t)row*DMODEL + col) =
                make_float2(acc[mt][nt][0] + b0, acc[mt][nt][1] + b1);
            *(float2*)(out + (size_t)(row+8)*DMODEL + col) =
                make_float2(acc[mt][nt][2] + b0, acc[mt][nt][3] + b1);
        }
    }
}

// ---------------------------------------------------------------------------
// Causal flash attention, FA2-style. Block = (128 q rows, one (b,h)).
// 8 warps, each owns 16 full rows (m16 x n64) -> softmax fully in registers,
// P stays in registers (S-frag -> PV A-frag), no smem exchange, 1 barrier/tile.
// ---------------------------------------------------------------------------
#define AQ_OFF 0u          // Q: 128 rows x 128B = 16KB
#define AK_OFF 16384u      // K: 2 stages x 8KB
#define AV_OFF 32768u      // V: 2 stages x 8KB
#define ATTN_SMEM 49152

__global__ __launch_bounds__(256, 2) void attn_kernel()
{
    extern __shared__ unsigned char sm[];
    const uint32_t sb = s2u(sm);

    const int qt = (int)(gridDim.x - 1 - blockIdx.x);  // big tiles first
    const int bh = blockIdx.y;
    const int b  = bh >> 4;
    const int h  = bh & 15;

    const __half* Qp = g_q  + (size_t)bh*SEQ*DHEAD + (size_t)qt*128*DHEAD;
    const __half* Kp = g_k  + (size_t)bh*SEQ*DHEAD;
    const __half* Vt = g_vt + (size_t)bh*DHEAD*SEQ;

    const int t = threadIdx.x, lane = t & 31, warp = t >> 5;
    const int g = lane >> 2, tig = lane & 3;
    const int r_lo = warp*16 + g, r_hi = r_lo + 8;   // block-local q rows

    // staging maps
    uint32_t q_dst[4]; const __half* q_src[4];
    #pragma unroll
    for (int j = 0; j < 4; j++) {
        const int id = t*4 + j, r = id >> 3, c = id & 7;
        q_dst[j] = sb + AQ_OFF + (uint32_t)(r*128 + ((c ^ (r&7))*16));
        q_src[j] = Qp + (size_t)r*DHEAD + c*8;
    }
    uint32_t kv_dst[2]; int kv_r[2], kv_c[2];
    #pragma unroll
    for (int j = 0; j < 2; j++) {
        const int id = t*2 + j;
        kv_r[j] = id >> 3; kv_c[j] = id & 7;
        kv_dst[j] = (uint32_t)(kv_r[j]*128 + ((kv_c[j] ^ (kv_r[j]&7))*16));
    }

    // prologue: Q + K0 + V0
    #pragma unroll
    for (int j = 0; j < 4; j++) cpa16(q_dst[j], q_src[j]);
    #pragma unroll
    for (int j = 0; j < 2; j++) {
        cpa16(sb + AK_OFF + kv_dst[j], Kp + (size_t)kv_r[j]*DHEAD + kv_c[j]*8);
        cpa16(sb + AV_OFF + kv_dst[j], Vt + (size_t)kv_r[j]*SEQ + kv_c[j]*8);
    }
    cpa_commit();
    cpa_wait<0>();

    float m0 = -1e30f, m1 = -1e30f, l0 = 0.f, l1 = 0.f;
    float oacc[8][4];
    #pragma unroll
    for (int i = 0; i < 8; i++)
        #pragma unroll
        for (int j = 0; j < 4; j++) oacc[i][j] = 0.f;

    const int nkv = 2*qt + 2;   // 64-key tiles
    for (int kt = 0; kt < nkv; kt++) {
        __syncthreads();   // publish stage(cur); prev iter's reads complete
        const int cur = kt & 1, nxt = cur ^ 1;
        const bool more = (kt + 1 < nkv);

        if (more) {
            const __half* Kn = Kp + (size_t)(kt+1)*64*DHEAD;
            #pragma unroll
            for (int j = 0; j < 2; j++) {
                cpa16(sb + AK_OFF + (uint32_t)nxt*8192u + kv_dst[j],
                      Kn + (size_t)kv_r[j]*DHEAD + kv_c[j]*8);
                cpa16(sb + AV_OFF + (uint32_t)nxt*8192u + kv_dst[j],
                      Vt + (size_t)kv_r[j]*SEQ + (kt+1)*64 + kv_c[j]*8);
            }
        }
        cpa_commit();

        const uint32_t ks = sb + AK_OFF + (uint32_t)cur*8192u;
        const uint32_t vs = sb + AV_OFF + (uint32_t)cur*8192u;

        // S = Q * K^T  (m=16/warp, n=64 keys, k=64 d)
        float sacc[8][4];
        #pragma unroll
        for (int i = 0; i < 8; i++)
            #pragma unroll
            for (int j = 0; j < 4; j++) sacc[i][j] = 0.f;

        #pragma unroll
        for (int s = 0; s < 4; s++) {
            const int kc = s*2;
            unsigned af[4], bk[4][4];
            ldsm4(af, frag_addr(sb + AQ_OFF, warp*16, kc, lane));
            #pragma unroll
            for (int nb = 0; nb < 4; nb++)
                ldsm4(bk[nb], frag_addr(ks, nb*16, kc, lane));
            #pragma unroll
            for (int nt = 0; nt < 8; nt++) {
                const unsigned* bsrc = bk[nt >> 1];
                unsigned bb[2] = { bsrc[nt & 1], bsrc[(nt & 1) + 2] };
                mma_f16(sacc[nt], af, bb);
            }
        }

        // causal mask: only top two kv tiles ((kt>>1)==qt). reference uses -1e5.
        if ((kt >> 1) == qt) {
            const int koff = (kt & 1) * 64;
            #pragma unroll
            for (int nt = 0; nt < 8; nt++) {
                const int c = koff + nt*8 + 2*tig;
                if (c     > r_lo) sacc[nt][0] = -100000.0f;
                if (c + 1 > r_lo) sacc[nt][1] = -100000.0f;
                if (c     > r_hi) sacc[nt][2] = -100000.0f;
                if (c + 1 > r_hi) sacc[nt][3] = -100000.0f;
            }
        }

        // row stats fully in-warp (rows live in thread quads)
        float pm0 = -1e30f, pm1 = -1e30f;
        #pragma unroll
        for (int nt = 0; nt < 8; nt++) {
            pm0 = fmaxf(pm0, fmaxf(sacc[nt][0], sacc[nt][1]));
            pm1 = fmaxf(pm1, fmaxf(sacc[nt][2], sacc[nt][3]));
        }
        pm0 = fmaxf(pm0, __shfl_xor_sync(0xffffffffu, pm0, 1));
        pm0 = fmaxf(pm0, __shfl_xor_sync(0xffffffffu, pm0, 2));
        pm1 = fmaxf(pm1, __shfl_xor_sync(0xffffffffu, pm1, 1));
        pm1 = fmaxf(pm1, __shfl_xor_sync(0xffffffffu, pm1, 2));

        const float mn0 = fmaxf(m0, pm0), mn1 = fmaxf(m1, pm1);
        const float f0 = __expf(m0 - mn0), f1 = __expf(m1 - mn1);
        m0 = mn0; m1 = mn1;

        // p = exp(s - m); P stays in registers as PV A-fragments
        unsigned ph[8][2];
        float ps0 = 0.f, ps1 = 0.f;
        #pragma unroll
        for (int nt = 0; nt < 8; nt++) {
            const float p0 = __expf(sacc[nt][0] - mn0);
            const float p1 = __expf(sacc[nt][1] - mn0);
            const float p2 = __expf(sacc[nt][2] - mn1);
            const float p3 = __expf(sacc[nt][3] - mn1);
            ps0 += p0 + p1; ps1 += p2 + p3;
            ph[nt][0] = h2u(__floats2half2_rn(p0, p1));
            ph[nt][1] = h2u(__floats2half2_rn(p2, p3));
            oacc[nt][0] *= f0; oacc[nt][1] *= f0;
            oacc[nt][2] *= f1; oacc[nt][3] *= f1;
        }
        ps0 += __shfl_xor_sync(0xffffffffu, ps0, 1);
        ps0 += __shfl_xor_sync(0xffffffffu, ps0, 2);
        ps1 += __shfl_xor_sync(0xffffffffu, ps1, 1);
        ps1 += __shfl_xor_sync(0xffffffffu, ps1, 2);
        l0 = l0*f0 + ps0;
        l1 = l1*f1 + ps1;

        // O += P * V : A from registers, B = Vt[d][key]
        #pragma unroll
        for (int s = 0; s < 4; s++) {
            unsigned a[4] = { ph[2*s][0], ph[2*s][1], ph[2*s+1][0], ph[2*s+1][1] };
            unsigned bv[4][4];
            #pragma unroll
            for (int nb = 0; nb < 4; nb++)
                ldsm4(bv[nb], frag_addr(vs, nb*16, s*2, lane));
            #pragma unroll
            for (int nt = 0; nt < 8; nt++) {
                const unsigned* bsrc = bv[nt >> 1];
                unsigned bb[2] = { bsrc[nt & 1], bsrc[(nt & 1) + 2] };
                mma_f16(oacc[nt], a, bb);
            }
        }
        cpa_wait<0>();   // next K/V landed before loop-top sync
    }

    // normalize + write g_att (fp16): d = nt*8 + 2tig
    const float inv0 = 1.0f / l0, inv1 = 1.0f / l1;
    __half* outp = g_att + ((size_t)b*SEQ + (size_t)qt*128)*DMODEL + h*DHEAD;
    #pragma unroll
    for (int nt = 0; nt < 8; nt++) {
        const int d = nt*8 + 2*tig;
        *(__half2*)(outp + (size_t)r_lo*DMODEL + d) =
            __floats2half2_rn(oacc[nt][0]*inv0, oacc[nt][1]*inv0);
        *(__half2*)(outp + (size_t)r_hi*DMODEL + d) =
            __floats2half2_rn(oacc[nt][2]*inv1, oacc[nt][3]*inv1);
    }
}

extern "C" void kernel_launch(void* const* d_in, const int* in_sizes, int n_in,
                              void* d_out, int out_size)
{
    const float* x  = (const float*)d_in[0];
    const float* Qw = (const float*)d_in[1];
    const float* Qb = (const float*)d_in[2];
    const float* Kw = (const float*)d_in[3];
    const float* Kb = (const float*)d_in[4];
    const float* Vw = (const float*)d_in[5];
    const float* Vb = (const float*)d_in[6];
    const float* Ow = (const float*)d_in[7];
    const float* Ob = (const float*)d_in[8];
    float* out = (float*)d_out;

    __half* d_wq; cudaGetSymbolAddress((void**)&d_wq, g_wqh);
    __half* d_wk; cudaGetSymbolAddress((void**)&d_wk, g_wkh);
    __half* d_wv; cudaGetSymbolAddress((void**)&d_wv, g_wvh);
    __half* d_wo; cudaGetSymbolAddress((void**)&d_wo, g_woh);

    // prework: fp16 conversions + weight transposes
    cvt_x_kernel<<<2048, 256>>>(x);
    trw_kernel<<<dim3(2, 32, NH), dim3(32, 8)>>>(Qw, d_wq, DMODEL, DHEAD);
    trw_kernel<<<dim3(2, 32, NH), dim3(32, 8)>>>(Kw, d_wk, DMODEL, DHEAD);
    trw_kernel<<<dim3(2, 32, NH), dim3(32, 8)>>>(Vw, d_wv, DMODEL, DHEAD);
    trw_kernel<<<dim3(32, 32, 1), dim3(32, 8)>>>(Ow, d_wo, DMODEL, DMODEL);

    cudaFuncSetAttribute(qkv_kernel,
                         cudaFuncAttributeMaxDynamicSharedMemorySize, GEMM_SMEM);
    cudaFuncSetAttribute(oproj_kernel,
                         cudaFuncAttributeMaxDynamicSharedMemorySize, GEMM_SMEM);
    cudaFuncSetAttribute(attn_kernel,
                         cudaFuncAttributeMaxDynamicSharedMemorySize, ATTN_SMEM);

    // QKV projection: 64 m-tiles x 24 (proj x 8 col-tiles)
    qkv_kernel<<<dim3(64, 24), 256, GEMM_SMEM>>>(Qb, Kb, Vb);

    // V transpose for attention B-operand
    trv_kernel<<<dim3(64, 2, BATCH*NH), dim3(32, 8)>>>();

    // Flash attention: 16 q-tiles x 64 (b,h)
    attn_kernel<<<dim3(16, 64), 256, ATTN_SMEM>>>();

    // Output projection: 64 m-tiles x 8 n-tiles
    oproj_kernel<<<dim3(64, 8), 256, GEMM_SMEM>>>(Ob, out);
}